// round 3
// baseline (speedup 1.0000x reference)
#include <cuda_runtime.h>
#include <cstdint>

#define NN   500000
#define FD   128
#define IN0  144
#define NG   2048
#define EPSV 1e-5f
#define TM   128
#define WST  132          // padded stride (weights / h / z tiles), 16B-aligned
#define XST  148          // padded stride for x0 tile

typedef unsigned long long ull;

// ---------------- scratch (static device globals) ----------------
__device__ __align__(16) float g_z[(size_t)NN * FD];      // 256 MB
__device__ __align__(16) float g_pt[(size_t)NN * 16];     // 32 MB transposed pers0
__device__ __align__(16) float g_xsum[NG * IN0];
__device__ __align__(16) float g_cnt[NG];
__device__ __align__(16) float g_c1[NG * FD];
__device__ __align__(16) float g_c2[NG * FD];
__device__ __align__(16) float g_hsum[NG * FD];
__device__ __align__(16) float g_zsum[NG * FD];
__device__ __align__(16) int   g_start[NG + 1];
__device__ __align__(16) float g_colsum[FD];
__device__ __align__(16) float g_colsq[FD];
__device__ __align__(16) float g_scale[FD];
__device__ __align__(16) float g_shift[FD];

// ---------------- f32x2 helpers ----------------
__device__ __forceinline__ ull pack2(float lo, float hi) {
    ull r;
    asm("mov.b64 %0, {%1,%2};" : "=l"(r) : "f"(lo), "f"(hi));
    return r;
}
__device__ __forceinline__ void unpack2(ull v, float& lo, float& hi) {
    asm("mov.b64 {%0,%1}, %2;" : "=f"(lo), "=f"(hi) : "l"(v));
}
__device__ __forceinline__ ull ffma2(ull a, ull b, ull c) {
    ull d;
    asm("fma.rn.f32x2 %0, %1, %2, %3;" : "=l"(d) : "l"(a), "l"(b), "l"(c));
    return d;
}

// ---------------- K0: zero accumulators, init segment starts ----------------
__global__ void k_init() {
    int i = blockIdx.x * blockDim.x + threadIdx.x;
    if (i < NG * FD) { g_hsum[i] = 0.f; g_zsum[i] = 0.f; }
    if (i < FD) { g_colsum[i] = 0.f; g_colsq[i] = 0.f; }
    if (i <= NG) g_start[i] = NN;
}

// ---------------- K0b: transpose pers0 [8][N][2] -> g_pt [N][16] -------------
__global__ void k_tr(const float2* __restrict__ p0) {
    __shared__ float sh[32 * 18];
    int t = threadIdx.x;
    int n0 = blockIdx.x * 32;
    int p = t >> 5, lane = t & 31;
    int n = n0 + lane;
    if (n < NN) {
        float2 v = p0[(size_t)p * NN + n];
        sh[lane * 18 + 2 * p]     = v.x;
        sh[lane * 18 + 2 * p + 1] = v.y;
    }
    __syncthreads();
    for (int idx = t; idx < 512; idx += 256) {
        int r = idx >> 4, c = idx & 15;
        int nn = n0 + r;
        if (nn < NN) g_pt[(size_t)nn * 16 + c] = sh[r * 18 + c];
    }
}

// ---------------- K0c: segment boundaries (batch sorted) ----------------
__global__ void k_bounds(const int* __restrict__ batch) {
    int n = blockIdx.x * blockDim.x + threadIdx.x;
    if (n >= NN) return;
    int b = batch[n];
    int prev = (n == 0) ? -1 : batch[n - 1];
    for (int g = prev + 1; g <= b; g++) g_start[g] = n;
}

// ---------------- K1: per-segment column sums of x0 (no atomics) -------------
__global__ void k_segsum(const float* __restrict__ x) {
    __shared__ float sh[384];
    int g = blockIdx.x, t = threadIdx.x;
    int s = g_start[g], e = g_start[g + 1];
    float acc = 0.f;
    if (t < 256) {
        int c = t & 127;
        #pragma unroll 4
        for (int n = s + (t >> 7); n < e; n += 2) acc += x[(size_t)n * FD + c];
    } else {
        int u = t - 256;
        int c = u & 15;
        #pragma unroll 2
        for (int n = s + (u >> 4); n < e; n += 8) acc += g_pt[(size_t)n * 16 + c];
    }
    sh[t] = acc;
    __syncthreads();
    if (t < 128) {
        g_xsum[g * IN0 + t] = sh[t] + sh[t + 128];
    } else if (t < 144) {
        int c = t - 128;
        float a = 0.f;
        #pragma unroll
        for (int j = 0; j < 8; j++) a += sh[256 + j * 16 + c];
        g_xsum[g * IN0 + t] = a;
    }
    if (t == 0) g_cnt[g] = (float)(e - s);
}

// ---------------- K2/K4: c = gb - (sum/cnt) @ lw^T ----------------
__global__ void k_corr(int which, const float* __restrict__ lw,
                       const float* __restrict__ gb, int K, int padK) {
    extern __shared__ float dsm[];
    float* shw = dsm;              // FD * padK
    float* shm = dsm + FD * padK;  // K
    const float* msum = which ? g_hsum : g_xsum;
    float* cout       = which ? g_c2   : g_c1;
    int t = threadIdx.x;
    for (int idx = t; idx < FD * K; idx += FD) {
        int j = idx / K;
        int k = idx - j * K;
        shw[j * padK + k] = lw[idx];
    }
    float gbv = gb[t];
    for (int gg = 0; gg < 16; gg++) {
        int g = blockIdx.x * 16 + gg;
        float inv = 1.f / fmaxf(g_cnt[g], 1.f);
        __syncthreads();
        for (int k = t; k < K; k += FD) shm[k] = msum[g * K + k] * inv;
        __syncthreads();
        float acc = 0.f;
        #pragma unroll 4
        for (int k = 0; k < K; k++) acc += shm[k] * shw[t * padK + k];
        cout[g * FD + t] = gbv - acc;
    }
}

// ---------------- GEMM inner: 8 rows x 8 cols per thread ----------------
template <int K, int AS>
__device__ __forceinline__ void gemm_acc(const float* __restrict__ a_base,
                                         const float* __restrict__ w,
                                         int tx, int ty, ull acc[8][4]) {
    #pragma unroll
    for (int i = 0; i < 8; i++)
        #pragma unroll
        for (int j = 0; j < 4; j++) acc[i][j] = 0ull;
    #pragma unroll 2
    for (int k = 0; k < K; k += 2) {
        float2 xv[8];
        #pragma unroll
        for (int i = 0; i < 8; i++)
            xv[i] = *(const float2*)(a_base + (ty + 16 * i) * AS + k);
        #pragma unroll
        for (int kk = 0; kk < 2; kk++) {
            const float* wb = w + (k + kk) * WST + (tx << 3);
            ulonglong2 b01 = *(const ulonglong2*)(wb);
            ulonglong2 b23 = *(const ulonglong2*)(wb + 4);
            #pragma unroll
            for (int i = 0; i < 8; i++) {
                float xs = kk ? xv[i].y : xv[i].x;
                ull xx = pack2(xs, xs);
                acc[i][0] = ffma2(xx, b01.x, acc[i][0]);
                acc[i][1] = ffma2(xx, b01.y, acc[i][1]);
                acc[i][2] = ffma2(xx, b23.x, acc[i][2]);
                acc[i][3] = ffma2(xx, b23.y, acc[i][3]);
            }
        }
    }
}

// ---------------- K3: persistent fused main kernel ----------------
__global__ __launch_bounds__(256, 1)
void k_main(const float* __restrict__ x, const int* __restrict__ batch,
            const float* __restrict__ g1w, const float* __restrict__ g2w) {
    extern __shared__ float dsm[];
    float* sw1 = dsm;                   // IN0 * WST (transposed: [k][j])
    float* sw2 = sw1 + IN0 * WST;       // FD * WST
    float* sx  = sw2 + FD * WST;        // TM * XST (x0) reused stride WST for h/z
    int*   sb  = (int*)(sx + TM * XST); // TM

    int t = threadIdx.x;
    for (int idx = t; idx < FD * IN0; idx += 256) {
        int j = idx / IN0;
        int k = idx - j * IN0;
        sw1[k * WST + j] = g1w[idx];
    }
    for (int idx = t; idx < FD * FD; idx += 256) {
        int j = idx >> 7;
        int k = idx & 127;
        sw2[k * WST + j] = g2w[idx];
    }

    int tx = t & 15, ty = t >> 4;
    int c0 = tx << 3;                 // 8 consecutive columns per thread
    float csum[8], csq[8];
    #pragma unroll
    for (int j = 0; j < 8; j++) { csum[j] = 0.f; csq[j] = 0.f; }

    const int NT = (NN + TM - 1) / TM;
    ull acc[8][4];

    for (int tile = blockIdx.x; tile < NT; tile += gridDim.x) {
        int n0 = tile * TM;
        __syncthreads();  // prior tile's smem readers done
        // load x tile (128x128 via float4) + pt (128x16)
        for (int idx = t; idx < TM * 32; idx += 256) {
            int r = idx >> 5, q = idx & 31;
            int n = n0 + r;
            float4 v = (n < NN) ? *(const float4*)(x + (size_t)n * FD + q * 4)
                                : make_float4(0.f, 0.f, 0.f, 0.f);
            *(float4*)(sx + r * XST + q * 4) = v;
        }
        for (int idx = t; idx < TM * 4; idx += 256) {
            int r = idx >> 2, q = idx & 3;
            int n = n0 + r;
            float4 v = (n < NN) ? *(const float4*)(g_pt + (size_t)n * 16 + q * 4)
                                : make_float4(0.f, 0.f, 0.f, 0.f);
            *(float4*)(sx + r * XST + FD + q * 4) = v;
        }
        if (t < TM) {
            int n = n0 + t;
            sb[t] = (n < NN) ? batch[n] : -1;
        }
        __syncthreads();

        // ---- GEMM1 ----
        gemm_acc<IN0, XST>(sx, sw1, tx, ty, acc);
        __syncthreads();  // GEMM1 reads of sx done

        // ---- epilogue 1: h = relu(acc + c1[batch]) into sx (stride WST) ----
        #pragma unroll
        for (int i = 0; i < 8; i++) {
            int r = ty + 16 * i;
            int g = sb[r];
            float4 cA = make_float4(0.f, 0.f, 0.f, 0.f);
            float4 cB = cA;
            if (g >= 0) {
                cA = *(const float4*)(g_c1 + g * FD + c0);
                cB = *(const float4*)(g_c1 + g * FD + c0 + 4);
            }
            float h0, h1, h2, h3, h4, h5, h6, h7;
            unpack2(acc[i][0], h0, h1); unpack2(acc[i][1], h2, h3);
            unpack2(acc[i][2], h4, h5); unpack2(acc[i][3], h6, h7);
            float* hp = sx + r * WST + c0;
            *(float4*)(hp)     = make_float4(fmaxf(h0 + cA.x, 0.f), fmaxf(h1 + cA.y, 0.f),
                                             fmaxf(h2 + cA.z, 0.f), fmaxf(h3 + cA.w, 0.f));
            *(float4*)(hp + 4) = make_float4(fmaxf(h4 + cB.x, 0.f), fmaxf(h5 + cB.y, 0.f),
                                             fmaxf(h6 + cB.z, 0.f), fmaxf(h7 + cB.w, 0.f));
        }
        __syncthreads();  // h tile ready

        // ---- hsum (run-length, batch sorted) ----
        {
            int c = t & 127;
            int rb = (t >> 7) * 64;
            float run = 0.f;
            int gc = -1;
            for (int r = rb; r < rb + 64; r++) {
                int g = sb[r];
                if (g != gc) {
                    if (gc >= 0) atomicAdd(&g_hsum[gc * FD + c], run);
                    run = 0.f;
                    gc = g;
                }
                if (g >= 0) run += sx[r * WST + c];
            }
            if (gc >= 0) atomicAdd(&g_hsum[gc * FD + c], run);
        }

        // ---- GEMM2 ----
        gemm_acc<FD, WST>(sx, sw2, tx, ty, acc);

        // ---- epilogue 2: z -> gmem + column stats in regs ----
        float zv[8][8];
        #pragma unroll
        for (int i = 0; i < 8; i++) {
            unpack2(acc[i][0], zv[i][0], zv[i][1]);
            unpack2(acc[i][1], zv[i][2], zv[i][3]);
            unpack2(acc[i][2], zv[i][4], zv[i][5]);
            unpack2(acc[i][3], zv[i][6], zv[i][7]);
            int r = ty + 16 * i;
            int n = n0 + r;
            if (n < NN) {
                float* zp = g_z + (size_t)n * FD + c0;
                *(float4*)(zp)     = make_float4(zv[i][0], zv[i][1], zv[i][2], zv[i][3]);
                *(float4*)(zp + 4) = make_float4(zv[i][4], zv[i][5], zv[i][6], zv[i][7]);
                #pragma unroll
                for (int j = 0; j < 8; j++) {
                    csum[j] += zv[i][j];
                    csq[j]  += zv[i][j] * zv[i][j];
                }
            }
        }
        __syncthreads();  // all GEMM2 reads of h done before overwrite

        // ---- z into smem for per-graph zsum ----
        #pragma unroll
        for (int i = 0; i < 8; i++) {
            int r = ty + 16 * i;
            float* zp = sx + r * WST + c0;
            *(float4*)(zp)     = make_float4(zv[i][0], zv[i][1], zv[i][2], zv[i][3]);
            *(float4*)(zp + 4) = make_float4(zv[i][4], zv[i][5], zv[i][6], zv[i][7]);
        }
        __syncthreads();

        // ---- zsum (run-length) ----
        {
            int c = t & 127;
            int rb = (t >> 7) * 64;
            float run = 0.f;
            int gc = -1;
            for (int r = rb; r < rb + 64; r++) {
                int g = sb[r];
                if (g != gc) {
                    if (gc >= 0) atomicAdd(&g_zsum[gc * FD + c], run);
                    run = 0.f;
                    gc = g;
                }
                if (g >= 0) run += sx[r * WST + c];
            }
            if (gc >= 0) atomicAdd(&g_zsum[gc * FD + c], run);
        }
    }

    // ---- final block reduction of column stats ----
    __syncthreads();
    float* red = sx;  // reuse
    #pragma unroll 1
    for (int j = 0; j < 8; j++) {
        red[t] = csum[j];
        __syncthreads();
        if (ty == 0) {
            float s = 0.f;
            #pragma unroll
            for (int yy = 0; yy < 16; yy++) s += red[yy * 16 + tx];
            atomicAdd(&g_colsum[c0 + j], s);
        }
        __syncthreads();
        red[t] = csq[j];
        __syncthreads();
        if (ty == 0) {
            float s = 0.f;
            #pragma unroll
            for (int yy = 0; yy < 16; yy++) s += red[yy * 16 + tx];
            atomicAdd(&g_colsq[c0 + j], s);
        }
        __syncthreads();
    }
}

// ---------------- K_post: fold c2 terms into column stats ----------------
// stats of y=z+c2[batch]: colsum += sum_g cnt*c2 ; colsq += sum_g (2*zsum*c2 + cnt*c2^2)
__global__ void k_post() {
    int c = threadIdx.x;           // 128
    int g0 = blockIdx.x * (NG / 16);
    float s = 0.f, q = 0.f;
    for (int g = g0; g < g0 + NG / 16; g++) {
        float cnt = g_cnt[g];
        float c2  = g_c2[g * FD + c];
        float zs  = g_zsum[g * FD + c];
        s += cnt * c2;
        q += 2.f * zs * c2 + cnt * c2 * c2;
    }
    atomicAdd(&g_colsum[c], s);
    atomicAdd(&g_colsq[c], q);
}

// ---------------- K5b: finalize BN scale/shift ----------------
__global__ void k_fin(const float* __restrict__ bng, const float* __restrict__ bnb) {
    int c = threadIdx.x;
    float mu  = g_colsum[c] / (float)NN;
    float var = g_colsq[c] / (float)NN - mu * mu;
    float inv = rsqrtf(var + EPSV);
    float sc  = bng[c] * inv;
    g_scale[c] = sc;
    g_shift[c] = bnb[c] - mu * sc;
}

// ---------------- K6: out = x + (z + c2[batch]) * scale + shift --------------
__global__ void k_out(const float* __restrict__ x, const int* __restrict__ batch,
                      float* __restrict__ out) {
    int idx = blockIdx.x * blockDim.x + threadIdx.x;
    if (idx >= NN * 32) return;
    int n = idx >> 5;
    int qd = idx & 31;
    int c0 = qd << 2;
    int g = batch[n];
    float4 zvv = *(const float4*)(g_z + (size_t)n * FD + c0);
    float4 xv = *(const float4*)(x + (size_t)n * FD + c0);
    float4 cv = *(const float4*)(g_c2 + g * FD + c0);
    float4 sc = *(const float4*)(g_scale + c0);
    float4 sh = *(const float4*)(g_shift + c0);
    float4 o;
    o.x = xv.x + (zvv.x + cv.x) * sc.x + sh.x;
    o.y = xv.y + (zvv.y + cv.y) * sc.y + sh.y;
    o.z = xv.z + (zvv.z + cv.z) * sc.z + sh.z;
    o.w = xv.w + (zvv.w + cv.w) * sc.w + sh.w;
    ((float4*)out)[idx] = o;
}

// ---------------- host ----------------
extern "C" void kernel_launch(void* const* d_in, const int* in_sizes, int n_in,
                              void* d_out, int out_size) {
    const float* x     = (const float*)d_in[0];
    const int*   batch = (const int*)d_in[1];
    const float* pers0 = (const float*)d_in[2];
    const float* g1w   = (const float*)d_in[3];
    const float* g1b   = (const float*)d_in[4];
    const float* l1w   = (const float*)d_in[5];
    const float* g2w   = (const float*)d_in[6];
    const float* g2b   = (const float*)d_in[7];
    const float* l2w   = (const float*)d_in[8];
    const float* bng   = (const float*)d_in[9];
    const float* bnb   = (const float*)d_in[10];
    float* out = (float*)d_out;

    int sms = 148;
    cudaDeviceGetAttribute(&sms, cudaDevAttrMultiProcessorCount, 0);

    const int smem_main  = (IN0 * WST + FD * WST + TM * XST) * 4 + TM * 4;  // 219,904 B
    const int smem_corr1 = (FD * 145 + IN0) * 4;
    const int smem_corr2 = (FD * 129 + FD) * 4;
    cudaFuncSetAttribute(k_main, cudaFuncAttributeMaxDynamicSharedMemorySize, smem_main);
    cudaFuncSetAttribute(k_corr, cudaFuncAttributeMaxDynamicSharedMemorySize, smem_corr1);

    k_init<<<(NG * FD + 255) / 256, 256>>>();
    k_tr<<<(NN + 31) / 32, 256>>>((const float2*)pers0);
    k_bounds<<<(NN + 255) / 256, 256>>>(batch);
    k_segsum<<<NG, 384>>>(x);
    k_corr<<<NG / 16, 128, smem_corr1>>>(0, l1w, g1b, IN0, 145);
    k_main<<<sms, 256, smem_main>>>(x, batch, g1w, g2w);
    k_corr<<<NG / 16, 128, smem_corr2>>>(1, l2w, g2b, FD, 129);
    k_post<<<16, 128>>>();
    k_fin<<<1, 128>>>(bng, bnb);
    k_out<<<(NN * 32 + 255) / 256, 256>>>(x, batch, out);
}

// round 5
// speedup vs baseline: 1.2504x; 1.2504x over previous
#include <cuda_runtime.h>
#include <cuda_bf16.h>
#include <cstdint>

#define NN   500000
#define FD   128
#define IN0  144
#define NG   2048
#define EPSV 1e-5f
#define TM   64
#define SST  132            // stage stride (floats), mult of 4 => float4-aligned rows
#define APST 73             // packed A stride (b32 units), odd => low conflicts

// ---- shared memory byte offsets ----
#define F1HI_OFF  0         // 9*16*32*8  = 36864
#define F1LO_OFF  36864
#define F2HI_OFF  73728     // 8*16*32*8  = 32768
#define F2LO_OFF  106496
#define STAGE_OFF 139264    // 64*132*4   = 33792
#define APHI_OFF  173056    // 64*73*4    = 18688
#define APLO_OFF  191744
#define SB_OFF    210432    // int[64]
#define SMEM_MAIN 210688

typedef unsigned long long ull;

// ---------------- scratch ----------------
__device__ __align__(16) float g_z[(size_t)NN * FD];
__device__ __align__(16) float g_xsum[NG * IN0];
__device__ __align__(16) float g_cnt[NG];
__device__ __align__(16) float g_c1[NG * FD];
__device__ __align__(16) float g_c2[NG * FD];
__device__ __align__(16) float g_hsum[NG * FD];
__device__ __align__(16) float g_zsum[NG * FD];
__device__ __align__(16) int   g_start[NG + 1];
__device__ __align__(16) float g_colsum[FD];
__device__ __align__(16) float g_colsq[FD];
__device__ __align__(16) float g_scale[FD];
__device__ __align__(16) float g_shift[FD];

// packed = {lo16 = bf16(a), hi16 = bf16(b)}
__device__ __forceinline__ uint32_t packbf(float a, float b) {
    uint32_t r;
    asm("cvt.rn.bf16x2.f32 %0, %1, %2;" : "=r"(r) : "f"(b), "f"(a));
    return r;
}

#define MMA_B16(acc, a0, a1, a2, a3, b0, b1) \
    asm volatile("mma.sync.aligned.m16n8k16.row.col.f32.bf16.bf16.f32 " \
        "{%0,%1,%2,%3}, {%4,%5,%6,%7}, {%8,%9}, {%0,%1,%2,%3};" \
        : "+f"((acc)[0]), "+f"((acc)[1]), "+f"((acc)[2]), "+f"((acc)[3]) \
        : "r"(a0), "r"(a1), "r"(a2), "r"(a3), "r"(b0), "r"(b1))

// ---------------- K0 ----------------
__global__ void k_init() {
    int i = blockIdx.x * blockDim.x + threadIdx.x;
    if (i < NG * FD) { g_hsum[i] = 0.f; g_zsum[i] = 0.f; }
    if (i < FD) { g_colsum[i] = 0.f; g_colsq[i] = 0.f; }
    if (i <= NG) g_start[i] = NN;
}

__global__ void k_bounds(const int* __restrict__ batch) {
    int n = blockIdx.x * blockDim.x + threadIdx.x;
    if (n >= NN) return;
    int b = batch[n];
    int prev = (n == 0) ? -1 : batch[n - 1];
    for (int g = prev + 1; g <= b; g++) g_start[g] = n;
}

// ---------------- K1: per-segment column sums of x0 ----------------
__global__ void k_segsum(const float* __restrict__ x, const float* __restrict__ pers0) {
    __shared__ float sh[384];
    int g = blockIdx.x, t = threadIdx.x;
    int s = g_start[g], e = g_start[g + 1];
    float acc = 0.f;
    if (t < 256) {
        int c = t & 127;
        #pragma unroll 4
        for (int n = s + (t >> 7); n < e; n += 2) acc += x[(size_t)n * FD + c];
    } else {
        int u = t - 256;
        int c = u & 15;
        int p = c >> 1, comp = c & 1;
        #pragma unroll 2
        for (int n = s + (u >> 4); n < e; n += 8)
            acc += pers0[((size_t)p * NN + n) * 2 + comp];
    }
    sh[t] = acc;
    __syncthreads();
    if (t < 128) {
        g_xsum[g * IN0 + t] = sh[t] + sh[t + 128];
    } else if (t < 144) {
        int c = t - 128;
        float a = 0.f;
        #pragma unroll
        for (int j = 0; j < 8; j++) a += sh[256 + j * 16 + c];
        g_xsum[g * IN0 + t] = a;
    }
    if (t == 0) g_cnt[g] = (float)(e - s);
}

// ---------------- K2/K4: c = gb - (sum/cnt) @ lw^T ----------------
__global__ void k_corr(int which, const float* __restrict__ lw,
                       const float* __restrict__ gb, int K, int padK) {
    extern __shared__ float dsm[];
    float* shw = dsm;
    float* shm = dsm + FD * padK;
    const float* msum = which ? g_hsum : g_xsum;
    float* cout       = which ? g_c2   : g_c1;
    int t = threadIdx.x;
    for (int idx = t; idx < FD * K; idx += FD) {
        int j = idx / K;
        int k = idx - j * K;
        shw[j * padK + k] = lw[idx];
    }
    float gbv = gb[t];
    for (int gg = 0; gg < 16; gg++) {
        int g = blockIdx.x * 16 + gg;
        float inv = 1.f / fmaxf(g_cnt[g], 1.f);
        __syncthreads();
        for (int k = t; k < K; k += FD) shm[k] = msum[g * K + k] * inv;
        __syncthreads();
        float acc = 0.f;
        #pragma unroll 4
        for (int k = 0; k < K; k++) acc += shm[k] * shw[t * padK + k];
        cout[g * FD + t] = gbv - acc;
    }
}

// ---------------- warp GEMM: D[16 x 64-half] += A(16xK) * B(Kx64) ----------------
template <int KC>
__device__ __forceinline__ void gemm_warp(const uint32_t* __restrict__ aphi,
                                          const uint32_t* __restrict__ aplo,
                                          const ull* __restrict__ fhi,
                                          const ull* __restrict__ flo,
                                          int r0, int ntbase, int lane,
                                          float acc[8][4]) {
    int lr = lane >> 2, lc = lane & 3;
    const uint32_t* h0p = aphi + (r0 + lr) * APST;
    const uint32_t* h1p = aphi + (r0 + lr + 8) * APST;
    const uint32_t* l0p = aplo + (r0 + lr) * APST;
    const uint32_t* l1p = aplo + (r0 + lr + 8) * APST;
    #pragma unroll 1
    for (int kc = 0; kc < KC; kc++) {
        int pa = kc * 8 + lc;
        uint32_t a0h = h0p[pa], a1h = h1p[pa], a2h = h0p[pa + 4], a3h = h1p[pa + 4];
        uint32_t a0l = l0p[pa], a1l = l1p[pa], a2l = l0p[pa + 4], a3l = l1p[pa + 4];
        #pragma unroll
        for (int nt = 0; nt < 8; nt++) {
            ull bh = fhi[(kc * 16 + ntbase + nt) * 32 + lane];
            ull bl = flo[(kc * 16 + ntbase + nt) * 32 + lane];
            uint32_t b0h = (uint32_t)bh, b1h = (uint32_t)(bh >> 32);
            uint32_t b0l = (uint32_t)bl, b1l = (uint32_t)(bl >> 32);
            MMA_B16(acc[nt], a0h, a1h, a2h, a3h, b0h, b1h);
            MMA_B16(acc[nt], a0h, a1h, a2h, a3h, b0l, b1l);
            MMA_B16(acc[nt], a0l, a1l, a2l, a3l, b0h, b1h);
        }
    }
}

// ---------------- K3: persistent fused main (bf16 HMMA, hi/lo split) ----------------
__global__ __launch_bounds__(256, 1)
void k_main(const float* __restrict__ x, const int* __restrict__ batch,
            const float* __restrict__ pers0,
            const float* __restrict__ g1w, const float* __restrict__ g2w) {
    extern __shared__ char sal[];
    ull*      f1hi  = (ull*)(sal + F1HI_OFF);
    ull*      f1lo  = (ull*)(sal + F1LO_OFF);
    ull*      f2hi  = (ull*)(sal + F2HI_OFF);
    ull*      f2lo  = (ull*)(sal + F2LO_OFF);
    float*    stage = (float*)(sal + STAGE_OFF);
    uint32_t* aphi  = (uint32_t*)(sal + APHI_OFF);
    uint32_t* aplo  = (uint32_t*)(sal + APLO_OFF);
    int*      sb    = (int*)(sal + SB_OFF);

    int t = threadIdx.x;
    int w = t >> 5, lane = t & 31;
    int r0 = (w >> 1) * 16;           // warp's 16 rows
    int h0 = (w & 1) * 64;            // warp's 64-col half
    int ntbase = h0 >> 3;

    // ---- one-time: build B fragments (hi/lo) in mma lane layout ----
    // entry (kc, nt, l): n = nt*8 + l/4 ; k0 = kc*16 + 2*(l%4)
    for (int idx = t; idx < 9 * 16 * 32; idx += 256) {
        int kc = idx >> 9, rem = idx & 511;
        int nt = rem >> 5, l = rem & 31;
        int n = nt * 8 + (l >> 2);
        int k0 = kc * 16 + ((l & 3) << 1);
        const float* wr = g1w + n * IN0;
        float w00 = wr[k0], w01 = wr[k0 + 1], w10 = wr[k0 + 8], w11 = wr[k0 + 9];
        uint32_t u0 = packbf(w00, w01), u1 = packbf(w10, w11);
        f1hi[idx] = (ull)u0 | ((ull)u1 << 32);
        float r00 = w00 - __uint_as_float(u0 << 16);
        float r01 = w01 - __uint_as_float(u0 & 0xffff0000u);
        float r10 = w10 - __uint_as_float(u1 << 16);
        float r11 = w11 - __uint_as_float(u1 & 0xffff0000u);
        uint32_t v0 = packbf(r00, r01), v1 = packbf(r10, r11);
        f1lo[idx] = (ull)v0 | ((ull)v1 << 32);
    }
    for (int idx = t; idx < 8 * 16 * 32; idx += 256) {
        int kc = idx >> 9, rem = idx & 511;
        int nt = rem >> 5, l = rem & 31;
        int n = nt * 8 + (l >> 2);
        int k0 = kc * 16 + ((l & 3) << 1);
        const float* wr = g2w + n * FD;
        float w00 = wr[k0], w01 = wr[k0 + 1], w10 = wr[k0 + 8], w11 = wr[k0 + 9];
        uint32_t u0 = packbf(w00, w01), u1 = packbf(w10, w11);
        f2hi[idx] = (ull)u0 | ((ull)u1 << 32);
        float r00 = w00 - __uint_as_float(u0 << 16);
        float r01 = w01 - __uint_as_float(u0 & 0xffff0000u);
        float r10 = w10 - __uint_as_float(u1 << 16);
        float r11 = w11 - __uint_as_float(u1 & 0xffff0000u);
        uint32_t v0 = packbf(r00, r01), v1 = packbf(r10, r11);
        f2lo[idx] = (ull)v0 | ((ull)v1 << 32);
    }

    int c = t & 127;                  // column for scans/stats
    float csum = 0.f, csq = 0.f;
    float acc[8][4];
    const int NT = (NN + TM - 1) / TM;
    const float2* pers2 = (const float2*)pers0;

    for (int tile = blockIdx.x; tile < NT; tile += gridDim.x) {
        int n0 = tile * TM;
        __syncthreads();                         // stage free (prev tile readers done)

        // ---- load x tile -> stage (float4 coalesced), batch -> sb ----
        for (int idx = t; idx < TM * 32; idx += 256) {
            int r = idx >> 5, q = idx & 31;
            int n = n0 + r;
            float4 v = (n < NN) ? *(const float4*)(x + (size_t)n * FD + q * 4)
                                : make_float4(0.f, 0.f, 0.f, 0.f);
            *(float4*)(stage + r * SST + q * 4) = v;
        }
        if (t < TM) {
            int n = n0 + t;
            sb[t] = (n < NN) ? batch[n] : -1;
        }
        __syncthreads();

        // ---- convert x0 rows -> packed bf16 hi/lo (A1) ----
        {
            int row = t >> 2, part = t & 3;
            int n = n0 + row;
            const float* srow = stage + row * SST;
            #pragma unroll
            for (int j = 0; j < 18; j++) {
                int pc = part * 18 + j;
                float a, b;
                if (pc < 64) {
                    a = srow[2 * pc];
                    b = srow[2 * pc + 1];
                } else {
                    int p = pc - 64;
                    float2 v = (n < NN) ? pers2[(size_t)p * NN + n] : make_float2(0.f, 0.f);
                    a = v.x; b = v.y;
                }
                uint32_t hp = packbf(a, b);
                float af = __uint_as_float(hp << 16);
                float bf_ = __uint_as_float(hp & 0xffff0000u);
                aphi[row * APST + pc] = hp;
                aplo[row * APST + pc] = packbf(a - af, b - bf_);
            }
        }
        __syncthreads();

        // ---- GEMM1 ----
        #pragma unroll
        for (int nt = 0; nt < 8; nt++)
            #pragma unroll
            for (int q = 0; q < 4; q++) acc[nt][q] = 0.f;
        gemm_warp<9>(aphi, aplo, f1hi, f1lo, r0, ntbase, lane, acc);
        __syncthreads();                         // A1 reads done before A2 overwrite

        // ---- epilogue 1: h = relu(acc + c1[g]) -> stage(fp32) + A2 hi/lo ----
        {
            int lr = lane >> 2, lc = lane & 3;
            int ra = r0 + lr, rb = ra + 8;
            int ga = sb[ra], gb_ = sb[rb];
            #pragma unroll
            for (int nt = 0; nt < 8; nt++) {
                int ncol = h0 + nt * 8 + 2 * lc;
                int pc = (ncol >> 1);
                float2 c1a = (ga >= 0) ? *(const float2*)(g_c1 + ga * FD + ncol)
                                       : make_float2(0.f, 0.f);
                float2 c1b = (gb_ >= 0) ? *(const float2*)(g_c1 + gb_ * FD + ncol)
                                        : make_float2(0.f, 0.f);
                float ha0 = fmaxf(acc[nt][0] + c1a.x, 0.f);
                float ha1 = fmaxf(acc[nt][1] + c1a.y, 0.f);
                float hb0 = fmaxf(acc[nt][2] + c1b.x, 0.f);
                float hb1 = fmaxf(acc[nt][3] + c1b.y, 0.f);
                *(float2*)(stage + ra * SST + ncol) = make_float2(ha0, ha1);
                *(float2*)(stage + rb * SST + ncol) = make_float2(hb0, hb1);
                uint32_t hpa = packbf(ha0, ha1);
                aphi[ra * APST + pc] = hpa;
                aplo[ra * APST + pc] = packbf(ha0 - __uint_as_float(hpa << 16),
                                              ha1 - __uint_as_float(hpa & 0xffff0000u));
                uint32_t hpb = packbf(hb0, hb1);
                aphi[rb * APST + pc] = hpb;
                aplo[rb * APST + pc] = packbf(hb0 - __uint_as_float(hpb << 16),
                                              hb1 - __uint_as_float(hpb & 0xffff0000u));
            }
        }
        __syncthreads();

        // ---- GEMM2 (reads A2 across both col-halves of own rows) ----
        #pragma unroll
        for (int nt = 0; nt < 8; nt++)
            #pragma unroll
            for (int q = 0; q < 4; q++) acc[nt][q] = 0.f;
        gemm_warp<8>(aphi, aplo, f2hi, f2lo, r0, ntbase, lane, acc);

        // ---- hsum (run-length over sorted batch; stage holds h) ----
        {
            float run = 0.f;
            int gc = -1;
            int rb2 = (t >> 7) * 32;
            for (int r = rb2; r < rb2 + 32; r++) {
                int g = sb[r];
                if (g != gc) {
                    if (gc >= 0) atomicAdd(&g_hsum[gc * FD + c], run);
                    run = 0.f;
                    gc = g;
                }
                if (g >= 0) run += stage[r * SST + c];
            }
            if (gc >= 0) atomicAdd(&g_hsum[gc * FD + c], run);
        }
        __syncthreads();                         // hsum readers done; stage free for z

        // ---- epilogue 2: z -> stage ----
        {
            int lr = lane >> 2, lc = lane & 3;
            int ra = r0 + lr, rb = ra + 8;
            #pragma unroll
            for (int nt = 0; nt < 8; nt++) {
                int ncol = h0 + nt * 8 + 2 * lc;
                *(float2*)(stage + ra * SST + ncol) = make_float2(acc[nt][0], acc[nt][1]);
                *(float2*)(stage + rb * SST + ncol) = make_float2(acc[nt][2], acc[nt][3]);
            }
        }
        __syncthreads();

        // ---- zsum + coalesced z write + column stats ----
        {
            float run = 0.f;
            int gc = -1;
            int rb2 = (t >> 7) * 32;
            for (int r = rb2; r < rb2 + 32; r++) {
                int g = sb[r];
                float v = stage[r * SST + c];
                if (g != gc) {
                    if (gc >= 0) atomicAdd(&g_zsum[gc * FD + c], run);
                    run = 0.f;
                    gc = g;
                }
                if (g >= 0) {
                    run += v;
                    csum += v;
                    csq += v * v;
                    g_z[(size_t)(n0 + r) * FD + c] = v;
                }
            }
            if (gc >= 0) atomicAdd(&g_zsum[gc * FD + c], run);
        }
    }

    atomicAdd(&g_colsum[c], csum);
    atomicAdd(&g_colsq[c], csq);
}

// ---------------- K_post: fold c2 terms into column stats ----------------
__global__ void k_post() {
    int c = threadIdx.x;
    int g0 = blockIdx.x * (NG / 16);
    float s = 0.f, q = 0.f;
    for (int g = g0; g < g0 + NG / 16; g++) {
        float cnt = g_cnt[g];
        float c2  = g_c2[g * FD + c];
        float zs  = g_zsum[g * FD + c];
        s += cnt * c2;
        q += 2.f * zs * c2 + cnt * c2 * c2;
    }
    atomicAdd(&g_colsum[c], s);
    atomicAdd(&g_colsq[c], q);
}

__global__ void k_fin(const float* __restrict__ bng, const float* __restrict__ bnb) {
    int c = threadIdx.x;
    float mu  = g_colsum[c] / (float)NN;
    float var = g_colsq[c] / (float)NN - mu * mu;
    float inv = rsqrtf(var + EPSV);
    float sc  = bng[c] * inv;
    g_scale[c] = sc;
    g_shift[c] = bnb[c] - mu * sc;
}

__global__ void k_out(const float* __restrict__ x, const int* __restrict__ batch,
                      float* __restrict__ out) {
    int idx = blockIdx.x * blockDim.x + threadIdx.x;
    if (idx >= NN * 32) return;
    int n = idx >> 5;
    int qd = idx & 31;
    int c0 = qd << 2;
    int g = batch[n];
    float4 zvv = *(const float4*)(g_z + (size_t)n * FD + c0);
    float4 xv = *(const float4*)(x + (size_t)n * FD + c0);
    float4 cv = *(const float4*)(g_c2 + g * FD + c0);
    float4 sc = *(const float4*)(g_scale + c0);
    float4 sh = *(const float4*)(g_shift + c0);
    float4 o;
    o.x = xv.x + (zvv.x + cv.x) * sc.x + sh.x;
    o.y = xv.y + (zvv.y + cv.y) * sc.y + sh.y;
    o.z = xv.z + (zvv.z + cv.z) * sc.z + sh.z;
    o.w = xv.w + (zvv.w + cv.w) * sc.w + sh.w;
    ((float4*)out)[idx] = o;
}

// ---------------- host ----------------
extern "C" void kernel_launch(void* const* d_in, const int* in_sizes, int n_in,
                              void* d_out, int out_size) {
    const float* x     = (const float*)d_in[0];
    const int*   batch = (const int*)d_in[1];
    const float* pers0 = (const float*)d_in[2];
    const float* g1w   = (const float*)d_in[3];
    const float* g1b   = (const float*)d_in[4];
    const float* l1w   = (const float*)d_in[5];
    const float* g2w   = (const float*)d_in[6];
    const float* g2b   = (const float*)d_in[7];
    const float* l2w   = (const float*)d_in[8];
    const float* bng   = (const float*)d_in[9];
    const float* bnb   = (const float*)d_in[10];
    float* out = (float*)d_out;

    int sms = 148;
    cudaDeviceGetAttribute(&sms, cudaDevAttrMultiProcessorCount, 0);

    const int smem_corr1 = (FD * 145 + IN0) * 4;
    const int smem_corr2 = (FD * 129 + FD) * 4;
    cudaFuncSetAttribute(k_main, cudaFuncAttributeMaxDynamicSharedMemorySize, SMEM_MAIN);
    cudaFuncSetAttribute(k_corr, cudaFuncAttributeMaxDynamicSharedMemorySize, smem_corr1);

    k_init<<<(NG * FD + 255) / 256, 256>>>();
    k_bounds<<<(NN + 255) / 256, 256>>>(batch);
    k_segsum<<<NG, 384>>>(x, pers0);
    k_corr<<<NG / 16, 128, smem_corr1>>>(0, l1w, g1b, IN0, 145);
    k_main<<<sms, 256, SMEM_MAIN>>>(x, batch, pers0, g1w, g2w);
    k_corr<<<NG / 16, 128, smem_corr2>>>(1, l2w, g2b, FD, 129);
    k_post<<<16, 128>>>();
    k_fin<<<1, 128>>>(bng, bnb);
    k_out<<<(NN * 32 + 255) / 256, 256>>>(x, batch, out);
}

// round 7
// speedup vs baseline: 1.6385x; 1.3103x over previous
#include <cuda_runtime.h>
#include <cuda_bf16.h>
#include <cstdint>

#define NN   500000
#define FD   128
#define IN0  144
#define NG   2048
#define EPSV 1e-5f
#define TM   64
#define SST  148            // stage stride (floats): 128 x-cols + 16 pers + pad
#define APST 73             // packed A stride (b32 units)

// ---- shared memory byte offsets (k_main) ----
#define F1HI_OFF  0         // 9*16*32*8  = 36864
#define F1LO_OFF  36864
#define F2HI_OFF  73728     // 8*16*32*8  = 32768
#define F2LO_OFF  106496
#define STAGE_OFF 139264    // 64*148*4   = 37888
#define APHI_OFF  177152    // 64*73*4    = 18688
#define APLO_OFF  195840
#define SB_OFF    214528    // int[64]
#define SMEM_MAIN 214784

#define CG 32               // graphs per k_corr block

typedef unsigned long long ull;

// ---------------- scratch ----------------
__device__ __align__(16) float g_z[(size_t)NN * FD];
__device__ __align__(16) float g_xsum[NG * IN0];
__device__ __align__(16) float g_cnt[NG];
__device__ __align__(16) float g_c1[NG * FD];
__device__ __align__(16) float g_c2[NG * FD];
__device__ __align__(16) float g_hsum[NG * FD];
__device__ __align__(16) float g_zsum[NG * FD];
__device__ __align__(16) int   g_start[NG + 1];
__device__ __align__(16) float g_colsum[FD];
__device__ __align__(16) float g_colsq[FD];
__device__ __align__(16) float g_scale[FD];
__device__ __align__(16) float g_shift[FD];

// packed = {lo16 = bf16(a), hi16 = bf16(b)}
__device__ __forceinline__ uint32_t packbf(float a, float b) {
    uint32_t r;
    asm("cvt.rn.bf16x2.f32 %0, %1, %2;" : "=r"(r) : "f"(b), "f"(a));
    return r;
}

#define MMA_B16(acc, a0, a1, a2, a3, b0, b1) \
    asm volatile("mma.sync.aligned.m16n8k16.row.col.f32.bf16.bf16.f32 " \
        "{%0,%1,%2,%3}, {%4,%5,%6,%7}, {%8,%9}, {%0,%1,%2,%3};" \
        : "+f"((acc)[0]), "+f"((acc)[1]), "+f"((acc)[2]), "+f"((acc)[3]) \
        : "r"(a0), "r"(a1), "r"(a2), "r"(a3), "r"(b0), "r"(b1))

// ---------------- K0: init ----------------
__global__ void k_init() {
    int i = blockIdx.x * blockDim.x + threadIdx.x;
    if (i < NG * FD) { g_hsum[i] = 0.f; g_zsum[i] = 0.f; }
    if (i <= NG) g_start[i] = NN;
}

// launch slot 5 (tiny) so k_main is the 6th launch for ncu -s 5 -c 1
__global__ void k_zero() {
    int i = threadIdx.x;
    g_colsum[i] = 0.f;
    g_colsq[i] = 0.f;
}

__global__ void k_bounds(const int* __restrict__ batch) {
    int n = blockIdx.x * blockDim.x + threadIdx.x;
    if (n >= NN) return;
    int b = batch[n];
    int prev = (n == 0) ? -1 : batch[n - 1];
    for (int g = prev + 1; g <= b; g++) g_start[g] = n;
}

// ---------------- K1: per-segment column sums of x0 ----------------
__global__ void k_segsum(const float* __restrict__ x, const float* __restrict__ pers0) {
    __shared__ float shx[4 * 128];
    __shared__ float shp[16 * 16];
    int g = blockIdx.x, t = threadIdx.x;
    int s = g_start[g], e = g_start[g + 1];
    const float2* x2 = (const float2*)x;
    const float2* p2 = (const float2*)pers0;
    if (t < 256) {
        int c2 = t & 63, ro = t >> 6;
        float ax = 0.f, ay = 0.f;
        int n = s + ro;
        #pragma unroll 4
        for (; n < e; n += 4) {
            float2 v = x2[(size_t)n * 64 + c2];
            ax += v.x; ay += v.y;
        }
        shx[ro * 128 + c2 * 2]     = ax;
        shx[ro * 128 + c2 * 2 + 1] = ay;
    } else {
        int u = t - 256;
        int p = u & 7, ro = u >> 3;        // 8 p x 16 rows
        float ax = 0.f, ay = 0.f;
        #pragma unroll 2
        for (int n = s + ro; n < e; n += 16) {
            float2 v = p2[(size_t)p * NN + n];
            ax += v.x; ay += v.y;
        }
        shp[ro * 16 + p * 2]     = ax;
        shp[ro * 16 + p * 2 + 1] = ay;
    }
    __syncthreads();
    if (t < 128) {
        float a = 0.f;
        #pragma unroll
        for (int r = 0; r < 4; r++) a += shx[r * 128 + t];
        g_xsum[g * IN0 + t] = a;
    } else if (t < 144) {
        int c = t - 128;
        float a = 0.f;
        #pragma unroll
        for (int j = 0; j < 16; j++) a += shp[j * 16 + c];
        g_xsum[g * IN0 + t] = a;
    }
    if (t == 0) g_cnt[g] = (float)(e - s);
}

// ---------------- K2/K4: c = gb - (sum/cnt) @ lw^T ----------------
__global__ void k_corr(int which, const float* __restrict__ lw,
                       const float* __restrict__ gb, int K, int padK) {
    extern __shared__ float dsm[];
    float* shw = dsm;                    // FD * padK
    float* shm = dsm + FD * padK;        // CG * K
    float* shc = shm + CG * K;           // CG
    const float* msum = which ? g_hsum : g_xsum;
    float* cout       = which ? g_c2   : g_c1;
    int t = threadIdx.x;                 // 128
    int gbase = blockIdx.x * CG;
    for (int idx = t; idx < FD * K; idx += 128) {
        int j = idx / K;
        int k = idx - j * K;
        shw[j * padK + k] = lw[idx];
    }
    for (int idx = t; idx < CG * K; idx += 128)
        shm[idx] = msum[gbase * K + idx];
    if (t < CG) shc[t] = 1.f / fmaxf(g_cnt[gbase + t], 1.f);
    __syncthreads();
    float gbv = gb[t];
    const float* wrow = shw + t * padK;
    for (int gg = 0; gg < CG; gg++) {
        const float* m = shm + gg * K;
        float a0 = 0.f, a1 = 0.f, a2 = 0.f, a3 = 0.f;
        #pragma unroll 9
        for (int k = 0; k < K; k += 4) {
            a0 += m[k]     * wrow[k];
            a1 += m[k + 1] * wrow[k + 1];
            a2 += m[k + 2] * wrow[k + 2];
            a3 += m[k + 3] * wrow[k + 3];
        }
        cout[(gbase + gg) * FD + t] = gbv - ((a0 + a1) + (a2 + a3)) * shc[gg];
    }
}

// ---------------- warp GEMM ----------------
template <int KC>
__device__ __forceinline__ void gemm_warp(const uint32_t* __restrict__ aphi,
                                          const uint32_t* __restrict__ aplo,
                                          const ull* __restrict__ fhi,
                                          const ull* __restrict__ flo,
                                          int r0, int ntbase, int lane,
                                          float acc[8][4]) {
    int lr = lane >> 2, lc = lane & 3;
    const uint32_t* h0p = aphi + (r0 + lr) * APST;
    const uint32_t* h1p = aphi + (r0 + lr + 8) * APST;
    const uint32_t* l0p = aplo + (r0 + lr) * APST;
    const uint32_t* l1p = aplo + (r0 + lr + 8) * APST;
    #pragma unroll 1
    for (int kc = 0; kc < KC; kc++) {
        int pa = kc * 8 + lc;
        uint32_t a0h = h0p[pa], a1h = h1p[pa], a2h = h0p[pa + 4], a3h = h1p[pa + 4];
        uint32_t a0l = l0p[pa], a1l = l1p[pa], a2l = l0p[pa + 4], a3l = l1p[pa + 4];
        #pragma unroll
        for (int nt = 0; nt < 8; nt++) {
            ull bh = fhi[(kc * 16 + ntbase + nt) * 32 + lane];
            ull bl = flo[(kc * 16 + ntbase + nt) * 32 + lane];
            uint32_t b0h = (uint32_t)bh, b1h = (uint32_t)(bh >> 32);
            uint32_t b0l = (uint32_t)bl, b1l = (uint32_t)(bl >> 32);
            MMA_B16(acc[nt], a0h, a1h, a2h, a3h, b0h, b1h);
            MMA_B16(acc[nt], a0h, a1h, a2h, a3h, b0l, b1l);
            MMA_B16(acc[nt], a0l, a1l, a2l, a3l, b0h, b1h);
        }
    }
}

// ---------------- K3: persistent fused main (bf16 HMMA, hi/lo split) ----------------
__global__ __launch_bounds__(256, 1)
void k_main(const float* __restrict__ x, const int* __restrict__ batch,
            const float* __restrict__ pers0,
            const float* __restrict__ g1w, const float* __restrict__ g2w) {
    extern __shared__ char sal[];
    ull*      f1hi  = (ull*)(sal + F1HI_OFF);
    ull*      f1lo  = (ull*)(sal + F1LO_OFF);
    ull*      f2hi  = (ull*)(sal + F2HI_OFF);
    ull*      f2lo  = (ull*)(sal + F2LO_OFF);
    float*    stage = (float*)(sal + STAGE_OFF);
    uint32_t* aphi  = (uint32_t*)(sal + APHI_OFF);
    uint32_t* aplo  = (uint32_t*)(sal + APLO_OFF);
    int*      sb    = (int*)(sal + SB_OFF);

    int t = threadIdx.x;
    int w = t >> 5, lane = t & 31;
    int r0 = (w >> 1) * 16;
    int h0 = (w & 1) * 64;
    int ntbase = h0 >> 3;

    // ---- one-time: B fragments (hi/lo) in mma lane layout ----
    for (int idx = t; idx < 9 * 16 * 32; idx += 256) {
        int kc = idx >> 9, rem = idx & 511;
        int nt = rem >> 5, l = rem & 31;
        int n = nt * 8 + (l >> 2);
        int k0 = kc * 16 + ((l & 3) << 1);
        const float* wr = g1w + n * IN0;
        float w00 = wr[k0], w01 = wr[k0 + 1], w10 = wr[k0 + 8], w11 = wr[k0 + 9];
        uint32_t u0 = packbf(w00, w01), u1 = packbf(w10, w11);
        f1hi[idx] = (ull)u0 | ((ull)u1 << 32);
        float r00 = w00 - __uint_as_float(u0 << 16);
        float r01 = w01 - __uint_as_float(u0 & 0xffff0000u);
        float r10 = w10 - __uint_as_float(u1 << 16);
        float r11 = w11 - __uint_as_float(u1 & 0xffff0000u);
        uint32_t v0 = packbf(r00, r01), v1 = packbf(r10, r11);
        f1lo[idx] = (ull)v0 | ((ull)v1 << 32);
    }
    for (int idx = t; idx < 8 * 16 * 32; idx += 256) {
        int kc = idx >> 9, rem = idx & 511;
        int nt = rem >> 5, l = rem & 31;
        int n = nt * 8 + (l >> 2);
        int k0 = kc * 16 + ((l & 3) << 1);
        const float* wr = g2w + n * FD;
        float w00 = wr[k0], w01 = wr[k0 + 1], w10 = wr[k0 + 8], w11 = wr[k0 + 9];
        uint32_t u0 = packbf(w00, w01), u1 = packbf(w10, w11);
        f2hi[idx] = (ull)u0 | ((ull)u1 << 32);
        float r00 = w00 - __uint_as_float(u0 << 16);
        float r01 = w01 - __uint_as_float(u0 & 0xffff0000u);
        float r10 = w10 - __uint_as_float(u1 << 16);
        float r11 = w11 - __uint_as_float(u1 & 0xffff0000u);
        uint32_t v0 = packbf(r00, r01), v1 = packbf(r10, r11);
        f2lo[idx] = (ull)v0 | ((ull)v1 << 32);
    }

    int c = t & 127;
    float csum = 0.f, csq = 0.f;
    float acc[8][4];
    const int NT = (NN + TM - 1) / TM;
    const float2* pers2 = (const float2*)pers0;

    // ---- prefetch registers ----
    float4 nx[8];
    float2 np[2];
    int nb = -1;

    // initial prefetch (tile = blockIdx.x)
    {
        int tile0 = blockIdx.x;
        if (tile0 < NT) {
            int n0 = tile0 * TM;
            #pragma unroll
            for (int j = 0; j < 8; j++) {
                int idx = t + j * 256;
                int r = idx >> 5, q = idx & 31;
                int n = n0 + r;
                nx[j] = (n < NN) ? *(const float4*)(x + (size_t)n * FD + q * 4)
                                 : make_float4(0.f, 0.f, 0.f, 0.f);
            }
            #pragma unroll
            for (int j = 0; j < 2; j++) {
                int idx = t + j * 256;
                int r = idx & 63, p = idx >> 6;
                int n = n0 + r;
                np[j] = (n < NN) ? pers2[(size_t)p * NN + n] : make_float2(0.f, 0.f);
            }
            if (t < TM) {
                int n = n0 + t;
                nb = (n < NN) ? batch[n] : -1;
            }
        }
    }

    for (int tile = blockIdx.x; tile < NT; tile += gridDim.x) {
        int n0 = tile * TM;
        __syncthreads();                       // stage free (prev tile's scans done)

        // ---- store prefetched tile into stage ----
        #pragma unroll
        for (int j = 0; j < 8; j++) {
            int idx = t + j * 256;
            int r = idx >> 5, q = idx & 31;
            *(float4*)(stage + r * SST + q * 4) = nx[j];
        }
        #pragma unroll
        for (int j = 0; j < 2; j++) {
            int idx = t + j * 256;
            int r = idx & 63, p = idx >> 6;
            *(float2*)(stage + r * SST + 128 + p * 2) = np[j];
        }
        if (t < TM) sb[t] = nb;
        __syncthreads();

        // ---- convert rows -> packed bf16 hi/lo (A1); all smem now ----
        {
            int row = t >> 2, part = t & 3;
            const float* srow = stage + row * SST;
            #pragma unroll
            for (int j = 0; j < 18; j++) {
                int pc = part * 18 + j;
                float a = srow[2 * pc];
                float b = srow[2 * pc + 1];
                uint32_t hp = packbf(a, b);
                float af = __uint_as_float(hp << 16);
                float bf_ = __uint_as_float(hp & 0xffff0000u);
                aphi[row * APST + pc] = hp;
                aplo[row * APST + pc] = packbf(a - af, b - bf_);
            }
        }
        __syncthreads();

        // ---- issue prefetch for next tile (hidden behind GEMM1/2) ----
        {
            int tn = tile + gridDim.x;
            if (tn < NT) {
                int m0 = tn * TM;
                #pragma unroll
                for (int j = 0; j < 8; j++) {
                    int idx = t + j * 256;
                    int r = idx >> 5, q = idx & 31;
                    int n = m0 + r;
                    nx[j] = (n < NN) ? *(const float4*)(x + (size_t)n * FD + q * 4)
                                     : make_float4(0.f, 0.f, 0.f, 0.f);
                }
                #pragma unroll
                for (int j = 0; j < 2; j++) {
                    int idx = t + j * 256;
                    int r = idx & 63, p = idx >> 6;
                    int n = m0 + r;
                    np[j] = (n < NN) ? pers2[(size_t)p * NN + n] : make_float2(0.f, 0.f);
                }
                if (t < TM) {
                    int n = m0 + t;
                    nb = (n < NN) ? batch[n] : -1;
                }
            }
        }

        // ---- GEMM1 ----
        #pragma unroll
        for (int nt = 0; nt < 8; nt++)
            #pragma unroll
            for (int q = 0; q < 4; q++) acc[nt][q] = 0.f;
        gemm_warp<9>(aphi, aplo, f1hi, f1lo, r0, ntbase, lane, acc);
        __syncthreads();                       // pair-warp A1 reads done

        // ---- epilogue 1: h = relu(acc + c1[g]) -> stage + A2 hi/lo ----
        {
            int lr = lane >> 2, lc = lane & 3;
            int ra = r0 + lr, rb = ra + 8;
            int ga = sb[ra], gb_ = sb[rb];
            #pragma unroll
            for (int nt = 0; nt < 8; nt++) {
                int ncol = h0 + nt * 8 + 2 * lc;
                int pc = (ncol >> 1);
                float2 c1a = (ga >= 0) ? *(const float2*)(g_c1 + ga * FD + ncol)
                                       : make_float2(0.f, 0.f);
                float2 c1b = (gb_ >= 0) ? *(const float2*)(g_c1 + gb_ * FD + ncol)
                                        : make_float2(0.f, 0.f);
                float ha0 = fmaxf(acc[nt][0] + c1a.x, 0.f);
                float ha1 = fmaxf(acc[nt][1] + c1a.y, 0.f);
                float hb0 = fmaxf(acc[nt][2] + c1b.x, 0.f);
                float hb1 = fmaxf(acc[nt][3] + c1b.y, 0.f);
                *(float2*)(stage + ra * SST + ncol) = make_float2(ha0, ha1);
                *(float2*)(stage + rb * SST + ncol) = make_float2(hb0, hb1);
                uint32_t hpa = packbf(ha0, ha1);
                aphi[ra * APST + pc] = hpa;
                aplo[ra * APST + pc] = packbf(ha0 - __uint_as_float(hpa << 16),
                                              ha1 - __uint_as_float(hpa & 0xffff0000u));
                uint32_t hpb = packbf(hb0, hb1);
                aphi[rb * APST + pc] = hpb;
                aplo[rb * APST + pc] = packbf(hb0 - __uint_as_float(hpb << 16),
                                              hb1 - __uint_as_float(hpb & 0xffff0000u));
            }
        }
        __syncthreads();

        // ---- GEMM2 ----
        #pragma unroll
        for (int nt = 0; nt < 8; nt++)
            #pragma unroll
            for (int q = 0; q < 4; q++) acc[nt][q] = 0.f;
        gemm_warp<8>(aphi, aplo, f2hi, f2lo, r0, ntbase, lane, acc);

        // ---- hsum (run-length; overlaps in-flight GEMM2 MMAs) ----
        {
            float run = 0.f;
            int gc = -1;
            int rb2 = (t >> 7) * 32;
            for (int r = rb2; r < rb2 + 32; r++) {
                int g = sb[r];
                if (g != gc) {
                    if (gc >= 0) atomicAdd(&g_hsum[gc * FD + c], run);
                    run = 0.f;
                    gc = g;
                }
                if (g >= 0) run += stage[r * SST + c];
            }
            if (gc >= 0) atomicAdd(&g_hsum[gc * FD + c], run);
        }
        __syncthreads();                       // stage free for z

        // ---- epilogue 2: z -> stage ----
        {
            int lr = lane >> 2, lc = lane & 3;
            int ra = r0 + lr, rb = ra + 8;
            #pragma unroll
            for (int nt = 0; nt < 8; nt++) {
                int ncol = h0 + nt * 8 + 2 * lc;
                *(float2*)(stage + ra * SST + ncol) = make_float2(acc[nt][0], acc[nt][1]);
                *(float2*)(stage + rb * SST + ncol) = make_float2(acc[nt][2], acc[nt][3]);
            }
        }
        __syncthreads();

        // ---- zsum + coalesced z write + column stats ----
        {
            float run = 0.f;
            int gc = -1;
            int rb2 = (t >> 7) * 32;
            for (int r = rb2; r < rb2 + 32; r++) {
                int g = sb[r];
                float v = stage[r * SST + c];
                if (g != gc) {
                    if (gc >= 0) atomicAdd(&g_zsum[gc * FD + c], run);
                    run = 0.f;
                    gc = g;
                }
                if (g >= 0) {
                    run += v;
                    csum += v;
                    csq += v * v;
                    g_z[(size_t)(n0 + r) * FD + c] = v;
                }
            }
            if (gc >= 0) atomicAdd(&g_zsum[gc * FD + c], run);
        }
    }

    atomicAdd(&g_colsum[c], csum);
    atomicAdd(&g_colsq[c], csq);
}

// ---------------- K_post: fold c2 terms into column stats ----------------
__global__ void k_post() {
    int c = threadIdx.x;
    int g0 = blockIdx.x * (NG / 16);
    float s = 0.f, q = 0.f;
    for (int g = g0; g < g0 + NG / 16; g++) {
        float cnt = g_cnt[g];
        float c2  = g_c2[g * FD + c];
        float zs  = g_zsum[g * FD + c];
        s += cnt * c2;
        q += 2.f * zs * c2 + cnt * c2 * c2;
    }
    atomicAdd(&g_colsum[c], s);
    atomicAdd(&g_colsq[c], q);
}

__global__ void k_fin(const float* __restrict__ bng, const float* __restrict__ bnb) {
    int c = threadIdx.x;
    float mu  = g_colsum[c] / (float)NN;
    float var = g_colsq[c] / (float)NN - mu * mu;
    float inv = rsqrtf(var + EPSV);
    float sc  = bng[c] * inv;
    g_scale[c] = sc;
    g_shift[c] = bnb[c] - mu * sc;
}

__global__ void k_out(const float* __restrict__ x, const int* __restrict__ batch,
                      float* __restrict__ out) {
    int idx = blockIdx.x * blockDim.x + threadIdx.x;
    if (idx >= NN * 32) return;
    int n = idx >> 5;
    int qd = idx & 31;
    int c0 = qd << 2;
    int g = batch[n];
    float4 zvv = *(const float4*)(g_z + (size_t)n * FD + c0);
    float4 xv = *(const float4*)(x + (size_t)n * FD + c0);
    float4 cv = *(const float4*)(g_c2 + g * FD + c0);
    float4 sc = *(const float4*)(g_scale + c0);
    float4 sh = *(const float4*)(g_shift + c0);
    float4 o;
    o.x = xv.x + (zvv.x + cv.x) * sc.x + sh.x;
    o.y = xv.y + (zvv.y + cv.y) * sc.y + sh.y;
    o.z = xv.z + (zvv.z + cv.z) * sc.z + sh.z;
    o.w = xv.w + (zvv.w + cv.w) * sc.w + sh.w;
    ((float4*)out)[idx] = o;
}

// ---------------- host ----------------
extern "C" void kernel_launch(void* const* d_in, const int* in_sizes, int n_in,
                              void* d_out, int out_size) {
    const float* x     = (const float*)d_in[0];
    const int*   batch = (const int*)d_in[1];
    const float* pers0 = (const float*)d_in[2];
    const float* g1w   = (const float*)d_in[3];
    const float* g1b   = (const float*)d_in[4];
    const float* l1w   = (const float*)d_in[5];
    const float* g2w   = (const float*)d_in[6];
    const float* g2b   = (const float*)d_in[7];
    const float* l2w   = (const float*)d_in[8];
    const float* bng   = (const float*)d_in[9];
    const float* bnb   = (const float*)d_in[10];
    float* out = (float*)d_out;

    int sms = 148;
    cudaDeviceGetAttribute(&sms, cudaDevAttrMultiProcessorCount, 0);

    const int smem_corr1 = (FD * 145 + CG * IN0 + CG) * 4;   // 92,800
    const int smem_corr2 = (FD * 129 + CG * FD + CG) * 4;
    cudaFuncSetAttribute(k_main, cudaFuncAttributeMaxDynamicSharedMemorySize, SMEM_MAIN);
    cudaFuncSetAttribute(k_corr, cudaFuncAttributeMaxDynamicSharedMemorySize, smem_corr1);

    k_init<<<(NG * FD + 255) / 256, 256>>>();                 // 1
    k_bounds<<<(NN + 255) / 256, 256>>>(batch);               // 2
    k_segsum<<<NG, 384>>>(x, pers0);                          // 3
    k_corr<<<NG / CG, 128, smem_corr1>>>(0, l1w, g1b, IN0, 145); // 4
    k_zero<<<1, 128>>>();                                     // 5
    k_main<<<sms, 256, SMEM_MAIN>>>(x, batch, pers0, g1w, g2w); // 6  <- ncu -s 5 -c 1
    k_corr<<<NG / CG, 128, smem_corr2>>>(1, l2w, g2b, FD, 129);  // 7
    k_post<<<16, 128>>>();                                    // 8
    k_fin<<<1, 128>>>(bng, bnb);                              // 9
    k_out<<<(NN * 32 + 255) / 256, 256>>>(x, batch, out);     // 10
}

// round 8
// speedup vs baseline: 1.8144x; 1.1074x over previous
#include <cuda_runtime.h>
#include <cuda_bf16.h>
#include <cstdint>

#define NN   500000
#define FD   128
#define IN0  144
#define NG   2048
#define EPSV 1e-5f
#define TM   64
#define SST  148            // stage stride (floats): 128 x-cols + 16 pers + pad
#define APST 73             // packed A stride (b32 units)

// ---- shared memory byte offsets (k_main) ----
#define F1HI_OFF  0         // 9*16*32*8  = 36864
#define F1LO_OFF  36864
#define F2HI_OFF  73728     // 8*16*32*8  = 32768
#define F2LO_OFF  106496
#define STAGE_OFF 139264    // 64*148*4   = 37888
#define APHI_OFF  177152    // 64*73*4    = 18688
#define APLO_OFF  195840
#define SB_OFF    214528    // int[64]
#define SMEM_MAIN 214784

#define CG 8                // graphs per k_corr block
#define FDP 132             // transposed W stride in k_corr

typedef unsigned long long ull;

// ---------------- scratch ----------------
__device__ __align__(16) float g_z[(size_t)NN * FD];
__device__ __align__(16) float g_xsum[NG * IN0];
__device__ __align__(16) float g_cnt[NG];
__device__ __align__(16) float g_c1[NG * FD];
__device__ __align__(16) float g_c2[NG * FD];
__device__ __align__(16) float g_hsum[NG * FD];
__device__ __align__(16) float g_zsum[NG * FD];
__device__ __align__(16) int   g_start[NG + 1];
__device__ __align__(16) float g_colsum[FD];
__device__ __align__(16) float g_colsq[FD];
__device__ __align__(16) float g_scale[FD];
__device__ __align__(16) float g_shift[FD];

// packed = {lo16 = bf16(a), hi16 = bf16(b)}
__device__ __forceinline__ uint32_t packbf(float a, float b) {
    uint32_t r;
    asm("cvt.rn.bf16x2.f32 %0, %1, %2;" : "=r"(r) : "f"(b), "f"(a));
    return r;
}

#define MMA_B16(acc, a0, a1, a2, a3, b0, b1) \
    asm volatile("mma.sync.aligned.m16n8k16.row.col.f32.bf16.bf16.f32 " \
        "{%0,%1,%2,%3}, {%4,%5,%6,%7}, {%8,%9}, {%0,%1,%2,%3};" \
        : "+f"((acc)[0]), "+f"((acc)[1]), "+f"((acc)[2]), "+f"((acc)[3]) \
        : "r"(a0), "r"(a1), "r"(a2), "r"(a3), "r"(b0), "r"(b1))

// ---------------- K_ib: init accumulators + segment bounds (merged, race-free) --
__global__ void k_ib(const int* __restrict__ batch) {
    int i = blockIdx.x * blockDim.x + threadIdx.x;
    if (i < NG * FD) { g_hsum[i] = 0.f; g_zsum[i] = 0.f; }
    if (i < FD) { g_colsum[i] = 0.f; g_colsq[i] = 0.f; }
    if (i < NN) {
        int b = batch[i];
        if (i == 0) {
            for (int g = 0; g <= b; g++) g_start[g] = 0;
        } else {
            int prev = batch[i - 1];
            for (int g = prev + 1; g <= b; g++) g_start[g] = i;
        }
        if (i == NN - 1) {
            for (int g = b + 1; g <= NG; g++) g_start[g] = NN;
        }
    }
}

// ---------------- K1: per-segment column sums of x0 ----------------
__global__ void k_segsum(const float* __restrict__ x, const float* __restrict__ pers0) {
    __shared__ float shx[4 * 128];
    __shared__ float shp[16 * 16];
    int g = blockIdx.x, t = threadIdx.x;
    int s = g_start[g], e = g_start[g + 1];
    const float2* x2 = (const float2*)x;
    const float2* p2 = (const float2*)pers0;
    if (t < 256) {
        int c2 = t & 63, ro = t >> 6;
        float ax = 0.f, ay = 0.f;
        int n = s + ro;
        #pragma unroll 4
        for (; n < e; n += 4) {
            float2 v = x2[(size_t)n * 64 + c2];
            ax += v.x; ay += v.y;
        }
        shx[ro * 128 + c2 * 2]     = ax;
        shx[ro * 128 + c2 * 2 + 1] = ay;
    } else {
        int u = t - 256;
        int p = u & 7, ro = u >> 3;
        float ax = 0.f, ay = 0.f;
        #pragma unroll 2
        for (int n = s + ro; n < e; n += 16) {
            float2 v = p2[(size_t)p * NN + n];
            ax += v.x; ay += v.y;
        }
        shp[ro * 16 + p * 2]     = ax;
        shp[ro * 16 + p * 2 + 1] = ay;
    }
    __syncthreads();
    if (t < 128) {
        float a = 0.f;
        #pragma unroll
        for (int r = 0; r < 4; r++) a += shx[r * 128 + t];
        g_xsum[g * IN0 + t] = a;
    } else if (t < 144) {
        int c = t - 128;
        float a = 0.f;
        #pragma unroll
        for (int j = 0; j < 16; j++) a += shp[j * 16 + c];
        g_xsum[g * IN0 + t] = a;
    }
    if (t == 0) g_cnt[g] = (float)(e - s);
}

// ---------------- K2/K4: c = gb - (sum/cnt) @ lw^T  (+ stat fold for WHICH=1) --
template <int WHICH, int K>
__global__ void k_corr(const float* __restrict__ lw, const float* __restrict__ gb) {
    extern __shared__ float dsm[];
    float* shw = dsm;                  // [K][FDP] transposed
    float* shm = shw + K * FDP;        // [CG][K]
    float* shc = shm + CG * K;         // [CG]
    const float* msum = WHICH ? g_hsum : g_xsum;
    float* cout       = WHICH ? g_c2   : g_c1;
    int t = threadIdx.x;               // 256
    int gbase = blockIdx.x * CG;
    // transposed W load (coalesced gmem; ~4-way STS conflicts, one-time)
    for (int idx = t; idx < FD * K; idx += 256) {
        int j = idx / K;
        int k = idx - j * K;
        shw[k * FDP + j] = lw[idx];
    }
    for (int idx = t; idx < CG * K; idx += 256)
        shm[idx] = msum[gbase * K + idx];
    if (t < CG) shc[t] = 1.f / fmaxf(g_cnt[gbase + t], 1.f);
    __syncthreads();

    int grp = t >> 7;                  // 0/1: graphs grp*4 .. grp*4+3
    int c = t & 127;
    int g0 = grp * 4;
    float acc[4][4];
    #pragma unroll
    for (int a = 0; a < 4; a++)
        #pragma unroll
        for (int b = 0; b < 4; b++) acc[a][b] = 0.f;

    const float4* m0 = (const float4*)(shm + (g0 + 0) * K);
    const float4* m1 = (const float4*)(shm + (g0 + 1) * K);
    const float4* m2 = (const float4*)(shm + (g0 + 2) * K);
    const float4* m3 = (const float4*)(shm + (g0 + 3) * K);
    #pragma unroll 4
    for (int k4 = 0; k4 < K / 4; k4++) {
        float4 v0 = m0[k4], v1 = m1[k4], v2 = m2[k4], v3 = m3[k4];  // broadcast
        const float* wp = shw + (k4 * 4) * FDP + c;
        float w0 = wp[0], w1 = wp[FDP], w2 = wp[2 * FDP], w3 = wp[3 * FDP];
        acc[0][0] += v0.x * w0; acc[0][1] += v0.y * w1; acc[0][2] += v0.z * w2; acc[0][3] += v0.w * w3;
        acc[1][0] += v1.x * w0; acc[1][1] += v1.y * w1; acc[1][2] += v1.z * w2; acc[1][3] += v1.w * w3;
        acc[2][0] += v2.x * w0; acc[2][1] += v2.y * w1; acc[2][2] += v2.z * w2; acc[2][3] += v2.w * w3;
        acc[3][0] += v3.x * w0; acc[3][1] += v3.y * w1; acc[3][2] += v3.z * w2; acc[3][3] += v3.w * w3;
    }
    float gbv = gb[c];
    float s = 0.f, q = 0.f;
    #pragma unroll
    for (int a = 0; a < 4; a++) {
        int g = gbase + g0 + a;
        float cv = gbv - ((acc[a][0] + acc[a][1]) + (acc[a][2] + acc[a][3])) * shc[g0 + a];
        cout[g * FD + c] = cv;
        if (WHICH) {
            float cnt = g_cnt[g];
            float zs  = g_zsum[g * FD + c];
            s += cnt * cv;
            q += 2.f * zs * cv + cnt * cv * cv;
        }
    }
    if (WHICH) {
        atomicAdd(&g_colsum[c], s);
        atomicAdd(&g_colsq[c], q);
    }
}

// ---------------- warp GEMM ----------------
template <int KC>
__device__ __forceinline__ void gemm_warp(const uint32_t* __restrict__ aphi,
                                          const uint32_t* __restrict__ aplo,
                                          const ull* __restrict__ fhi,
                                          const ull* __restrict__ flo,
                                          int r0, int ntbase, int lane,
                                          float acc[8][4]) {
    int lr = lane >> 2, lc = lane & 3;
    const uint32_t* h0p = aphi + (r0 + lr) * APST;
    const uint32_t* h1p = aphi + (r0 + lr + 8) * APST;
    const uint32_t* l0p = aplo + (r0 + lr) * APST;
    const uint32_t* l1p = aplo + (r0 + lr + 8) * APST;
    #pragma unroll 1
    for (int kc = 0; kc < KC; kc++) {
        int pa = kc * 8 + lc;
        uint32_t a0h = h0p[pa], a1h = h1p[pa], a2h = h0p[pa + 4], a3h = h1p[pa + 4];
        uint32_t a0l = l0p[pa], a1l = l1p[pa], a2l = l0p[pa + 4], a3l = l1p[pa + 4];
        #pragma unroll
        for (int nt = 0; nt < 8; nt++) {
            ull bh = fhi[(kc * 16 + ntbase + nt) * 32 + lane];
            ull bl = flo[(kc * 16 + ntbase + nt) * 32 + lane];
            uint32_t b0h = (uint32_t)bh, b1h = (uint32_t)(bh >> 32);
            uint32_t b0l = (uint32_t)bl, b1l = (uint32_t)(bl >> 32);
            MMA_B16(acc[nt], a0h, a1h, a2h, a3h, b0h, b1h);
            MMA_B16(acc[nt], a0h, a1h, a2h, a3h, b0l, b1l);
            MMA_B16(acc[nt], a0l, a1l, a2l, a3l, b0h, b1h);
        }
    }
}

// ---------------- K3: persistent fused main (bf16 HMMA, hi/lo split) ----------------
__global__ __launch_bounds__(256, 1)
void k_main(const float* __restrict__ x, const int* __restrict__ batch,
            const float* __restrict__ pers0,
            const float* __restrict__ g1w, const float* __restrict__ g2w) {
    extern __shared__ char sal[];
    ull*      f1hi  = (ull*)(sal + F1HI_OFF);
    ull*      f1lo  = (ull*)(sal + F1LO_OFF);
    ull*      f2hi  = (ull*)(sal + F2HI_OFF);
    ull*      f2lo  = (ull*)(sal + F2LO_OFF);
    float*    stage = (float*)(sal + STAGE_OFF);
    uint32_t* aphi  = (uint32_t*)(sal + APHI_OFF);
    uint32_t* aplo  = (uint32_t*)(sal + APLO_OFF);
    int*      sb    = (int*)(sal + SB_OFF);

    int t = threadIdx.x;
    int w = t >> 5, lane = t & 31;
    int r0 = (w >> 1) * 16;
    int h0 = (w & 1) * 64;
    int ntbase = h0 >> 3;
    int lr = lane >> 2, lc = lane & 3;

    // ---- one-time: B fragments (hi/lo) in mma lane layout ----
    for (int idx = t; idx < 9 * 16 * 32; idx += 256) {
        int kc = idx >> 9, rem = idx & 511;
        int nt = rem >> 5, l = rem & 31;
        int n = nt * 8 + (l >> 2);
        int k0 = kc * 16 + ((l & 3) << 1);
        const float* wr = g1w + n * IN0;
        float w00 = wr[k0], w01 = wr[k0 + 1], w10 = wr[k0 + 8], w11 = wr[k0 + 9];
        uint32_t u0 = packbf(w00, w01), u1 = packbf(w10, w11);
        f1hi[idx] = (ull)u0 | ((ull)u1 << 32);
        float r00 = w00 - __uint_as_float(u0 << 16);
        float r01 = w01 - __uint_as_float(u0 & 0xffff0000u);
        float r10 = w10 - __uint_as_float(u1 << 16);
        float r11 = w11 - __uint_as_float(u1 & 0xffff0000u);
        uint32_t v0 = packbf(r00, r01), v1 = packbf(r10, r11);
        f1lo[idx] = (ull)v0 | ((ull)v1 << 32);
    }
    for (int idx = t; idx < 8 * 16 * 32; idx += 256) {
        int kc = idx >> 9, rem = idx & 511;
        int nt = rem >> 5, l = rem & 31;
        int n = nt * 8 + (l >> 2);
        int k0 = kc * 16 + ((l & 3) << 1);
        const float* wr = g2w + n * FD;
        float w00 = wr[k0], w01 = wr[k0 + 1], w10 = wr[k0 + 8], w11 = wr[k0 + 9];
        uint32_t u0 = packbf(w00, w01), u1 = packbf(w10, w11);
        f2hi[idx] = (ull)u0 | ((ull)u1 << 32);
        float r00 = w00 - __uint_as_float(u0 << 16);
        float r01 = w01 - __uint_as_float(u0 & 0xffff0000u);
        float r10 = w10 - __uint_as_float(u1 << 16);
        float r11 = w11 - __uint_as_float(u1 & 0xffff0000u);
        uint32_t v0 = packbf(r00, r01), v1 = packbf(r10, r11);
        f2lo[idx] = (ull)v0 | ((ull)v1 << 32);
    }

    int c = t & 127;
    float csum = 0.f, csq = 0.f;
    float acc[8][4];
    const int NT = (NN + TM - 1) / TM;
    const float2* pers2 = (const float2*)pers0;

    // ---- prefetch registers ----
    float4 nx[8];
    float2 np[2];
    int nb = -1;
    float2 c1a[8], c1b[8];      // c1 corrections for epilogue 1

    {
        int tile0 = blockIdx.x;
        if (tile0 < NT) {
            int n0 = tile0 * TM;
            #pragma unroll
            for (int j = 0; j < 8; j++) {
                int idx = t + j * 256;
                int r = idx >> 5, q = idx & 31;
                int n = n0 + r;
                nx[j] = (n < NN) ? *(const float4*)(x + (size_t)n * FD + q * 4)
                                 : make_float4(0.f, 0.f, 0.f, 0.f);
            }
            #pragma unroll
            for (int j = 0; j < 2; j++) {
                int idx = t + j * 256;
                int r = idx & 63, p = idx >> 6;
                int n = n0 + r;
                np[j] = (n < NN) ? pers2[(size_t)p * NN + n] : make_float2(0.f, 0.f);
            }
            if (t < TM) {
                int n = n0 + t;
                nb = (n < NN) ? batch[n] : -1;
            }
        }
    }

    for (int tile = blockIdx.x; tile < NT; tile += gridDim.x) {
        int n0 = tile * TM;
        __syncthreads();

        // ---- store prefetched tile into stage ----
        #pragma unroll
        for (int j = 0; j < 8; j++) {
            int idx = t + j * 256;
            int r = idx >> 5, q = idx & 31;
            *(float4*)(stage + r * SST + q * 4) = nx[j];
        }
        #pragma unroll
        for (int j = 0; j < 2; j++) {
            int idx = t + j * 256;
            int r = idx & 63, p = idx >> 6;
            *(float2*)(stage + r * SST + 128 + p * 2) = np[j];
        }
        if (t < TM) sb[t] = nb;
        __syncthreads();

        // ---- prefetch c1 corrections (hidden behind convert + GEMM1) ----
        {
            int ra = r0 + lr, rb = ra + 8;
            int ga = sb[ra], gb_ = sb[rb];
            #pragma unroll
            for (int nt = 0; nt < 8; nt++) {
                int ncol = h0 + nt * 8 + 2 * lc;
                c1a[nt] = (ga >= 0) ? *(const float2*)(g_c1 + ga * FD + ncol)
                                    : make_float2(0.f, 0.f);
                c1b[nt] = (gb_ >= 0) ? *(const float2*)(g_c1 + gb_ * FD + ncol)
                                     : make_float2(0.f, 0.f);
            }
        }

        // ---- convert rows -> packed bf16 hi/lo (A1) ----
        {
            int row = t >> 2, part = t & 3;
            const float2* srow2 = (const float2*)(stage + row * SST);
            #pragma unroll
            for (int j = 0; j < 18; j++) {
                int pc = part * 18 + j;
                float2 v = srow2[pc];
                uint32_t hp = packbf(v.x, v.y);
                float af = __uint_as_float(hp << 16);
                float bf_ = __uint_as_float(hp & 0xffff0000u);
                aphi[row * APST + pc] = hp;
                aplo[row * APST + pc] = packbf(v.x - af, v.y - bf_);
            }
        }
        __syncthreads();

        // ---- issue next-tile prefetch (hidden behind GEMMs) ----
        {
            int tn = tile + gridDim.x;
            if (tn < NT) {
                int m0 = tn * TM;
                #pragma unroll
                for (int j = 0; j < 8; j++) {
                    int idx = t + j * 256;
                    int r = idx >> 5, q = idx & 31;
                    int n = m0 + r;
                    nx[j] = (n < NN) ? *(const float4*)(x + (size_t)n * FD + q * 4)
                                     : make_float4(0.f, 0.f, 0.f, 0.f);
                }
                #pragma unroll
                for (int j = 0; j < 2; j++) {
                    int idx = t + j * 256;
                    int r = idx & 63, p = idx >> 6;
                    int n = m0 + r;
                    np[j] = (n < NN) ? pers2[(size_t)p * NN + n] : make_float2(0.f, 0.f);
                }
                if (t < TM) {
                    int n = m0 + t;
                    nb = (n < NN) ? batch[n] : -1;
                }
            }
        }

        // ---- GEMM1 ----
        #pragma unroll
        for (int nt = 0; nt < 8; nt++)
            #pragma unroll
            for (int q = 0; q < 4; q++) acc[nt][q] = 0.f;
        gemm_warp<9>(aphi, aplo, f1hi, f1lo, r0, ntbase, lane, acc);
        __syncthreads();

        // ---- epilogue 1: h = relu(acc + c1) -> stage + A2 hi/lo ----
        {
            int ra = r0 + lr, rb = ra + 8;
            #pragma unroll
            for (int nt = 0; nt < 8; nt++) {
                int ncol = h0 + nt * 8 + 2 * lc;
                int pc = (ncol >> 1);
                float ha0 = fmaxf(acc[nt][0] + c1a[nt].x, 0.f);
                float ha1 = fmaxf(acc[nt][1] + c1a[nt].y, 0.f);
                float hb0 = fmaxf(acc[nt][2] + c1b[nt].x, 0.f);
                float hb1 = fmaxf(acc[nt][3] + c1b[nt].y, 0.f);
                *(float2*)(stage + ra * SST + ncol) = make_float2(ha0, ha1);
                *(float2*)(stage + rb * SST + ncol) = make_float2(hb0, hb1);
                uint32_t hpa = packbf(ha0, ha1);
                aphi[ra * APST + pc] = hpa;
                aplo[ra * APST + pc] = packbf(ha0 - __uint_as_float(hpa << 16),
                                              ha1 - __uint_as_float(hpa & 0xffff0000u));
                uint32_t hpb = packbf(hb0, hb1);
                aphi[rb * APST + pc] = hpb;
                aplo[rb * APST + pc] = packbf(hb0 - __uint_as_float(hpb << 16),
                                              hb1 - __uint_as_float(hpb & 0xffff0000u));
            }
        }
        __syncthreads();

        // ---- GEMM2 ----
        #pragma unroll
        for (int nt = 0; nt < 8; nt++)
            #pragma unroll
            for (int q = 0; q < 4; q++) acc[nt][q] = 0.f;
        gemm_warp<8>(aphi, aplo, f2hi, f2lo, r0, ntbase, lane, acc);

        // ---- hsum (run-length; overlaps in-flight MMAs) ----
        {
            float run = 0.f;
            int gc = -1;
            int rb2 = (t >> 7) * 32;
            for (int r = rb2; r < rb2 + 32; r++) {
                int g = sb[r];
                if (g != gc) {
                    if (gc >= 0) atomicAdd(&g_hsum[gc * FD + c], run);
                    run = 0.f;
                    gc = g;
                }
                if (g >= 0) run += stage[r * SST + c];
            }
            if (gc >= 0) atomicAdd(&g_hsum[gc * FD + c], run);
        }
        __syncthreads();

        // ---- epilogue 2: z -> stage ----
        {
            int ra = r0 + lr, rb = ra + 8;
            #pragma unroll
            for (int nt = 0; nt < 8; nt++) {
                int ncol = h0 + nt * 8 + 2 * lc;
                *(float2*)(stage + ra * SST + ncol) = make_float2(acc[nt][0], acc[nt][1]);
                *(float2*)(stage + rb * SST + ncol) = make_float2(acc[nt][2], acc[nt][3]);
            }
        }
        __syncthreads();

        // ---- zsum + coalesced z write + column stats ----
        {
            float run = 0.f;
            int gc = -1;
            int rb2 = (t >> 7) * 32;
            for (int r = rb2; r < rb2 + 32; r++) {
                int g = sb[r];
                float v = stage[r * SST + c];
                if (g != gc) {
                    if (gc >= 0) atomicAdd(&g_zsum[gc * FD + c], run);
                    run = 0.f;
                    gc = g;
                }
                if (g >= 0) {
                    run += v;
                    csum += v;
                    csq += v * v;
                    g_z[(size_t)(n0 + r) * FD + c] = v;
                }
            }
            if (gc >= 0) atomicAdd(&g_zsum[gc * FD + c], run);
        }
    }

    atomicAdd(&g_colsum[c], csum);
    atomicAdd(&g_colsq[c], csq);
}

__global__ void k_fin(const float* __restrict__ bng, const float* __restrict__ bnb) {
    int c = threadIdx.x;
    float mu  = g_colsum[c] / (float)NN;
    float var = g_colsq[c] / (float)NN - mu * mu;
    float inv = rsqrtf(var + EPSV);
    float sc  = bng[c] * inv;
    g_scale[c] = sc;
    g_shift[c] = bnb[c] - mu * sc;
}

__global__ void k_out(const float* __restrict__ x, const int* __restrict__ batch,
                      float* __restrict__ out) {
    int idx = blockIdx.x * blockDim.x + threadIdx.x;
    if (idx >= NN * 32) return;
    int n = idx >> 5;
    int qd = idx & 31;
    int c0 = qd << 2;
    int g = batch[n];
    float4 zvv = *(const float4*)(g_z + (size_t)n * FD + c0);
    float4 xv = *(const float4*)(x + (size_t)n * FD + c0);
    float4 cv = *(const float4*)(g_c2 + g * FD + c0);
    float4 sc = *(const float4*)(g_scale + c0);
    float4 sh = *(const float4*)(g_shift + c0);
    float4 o;
    o.x = xv.x + (zvv.x + cv.x) * sc.x + sh.x;
    o.y = xv.y + (zvv.y + cv.y) * sc.y + sh.y;
    o.z = xv.z + (zvv.z + cv.z) * sc.z + sh.z;
    o.w = xv.w + (zvv.w + cv.w) * sc.w + sh.w;
    ((float4*)out)[idx] = o;
}

// ---------------- host ----------------
extern "C" void kernel_launch(void* const* d_in, const int* in_sizes, int n_in,
                              void* d_out, int out_size) {
    const float* x     = (const float*)d_in[0];
    const int*   batch = (const int*)d_in[1];
    const float* pers0 = (const float*)d_in[2];
    const float* g1w   = (const float*)d_in[3];
    const float* g1b   = (const float*)d_in[4];
    const float* l1w   = (const float*)d_in[5];
    const float* g2w   = (const float*)d_in[6];
    const float* g2b   = (const float*)d_in[7];
    const float* l2w   = (const float*)d_in[8];
    const float* bng   = (const float*)d_in[9];
    const float* bnb   = (const float*)d_in[10];
    float* out = (float*)d_out;

    int sms = 148;
    cudaDeviceGetAttribute(&sms, cudaDevAttrMultiProcessorCount, 0);

    const int smem_corr1 = (IN0 * FDP + CG * IN0 + CG) * 4;   // ~81 KB
    const int smem_corr2 = (FD * FDP + CG * FD + CG) * 4;     // ~72 KB
    cudaFuncSetAttribute(k_main, cudaFuncAttributeMaxDynamicSharedMemorySize, SMEM_MAIN);
    cudaFuncSetAttribute(k_corr<0, IN0>, cudaFuncAttributeMaxDynamicSharedMemorySize, smem_corr1);
    cudaFuncSetAttribute(k_corr<1, FD>,  cudaFuncAttributeMaxDynamicSharedMemorySize, smem_corr2);

    k_ib<<<(NN + 255) / 256, 256>>>(batch);                        // 1
    k_segsum<<<NG, 384>>>(x, pers0);                               // 2
    k_corr<0, IN0><<<NG / CG, 256, smem_corr1>>>(l1w, g1b);        // 3
    k_main<<<sms, 256, SMEM_MAIN>>>(x, batch, pers0, g1w, g2w);    // 4
    k_corr<1, FD><<<NG / CG, 256, smem_corr2>>>(l2w, g2b);         // 5
    k_fin<<<1, 128>>>(bng, bnb);                                   // 6
    k_out<<<(NN * 32 + 255) / 256, 256>>>(x, batch, out);          // 7
}